// round 6
// baseline (speedup 1.0000x reference)
#include <cuda_runtime.h>
#include <cuda_bf16.h>

// WCSS: loss = mean_k [ (S2_k - ||S1_k||^2 / n_k) / (n_k * D) ]
//
// R5 post-mortem: scatter was smem-atomic bound (9.8us); main was
// latency/imbalance bound (~2.7TB/s). R6: warp-aggregated scatter
// (__match_any_sync), BATCH=32 (4KB in flight/warp), CHUNK=128
// (480 live blocks -> 3.2 CTAs/SM balance).

#define CHUNK 128          // columns per block == threads per block
#define TILE  128          // rows staged in smem per outer iteration
#define KMAX  16           // max classes (problem uses 10)
#define NMAX  16384        // max N (problem uses 8192)
#define BATCH 32           // independent LDGs per thread (MLP)

__device__ double g_S2[KMAX];     // per-class sum of squares
__device__ double g_M2[KMAX];     // per-class ||S1_k||^2
__device__ int    g_order[NMAX];  // row ids grouped by class
__device__ int    g_cnt[KMAX];
__device__ int    g_start[KMAX];

// ---------------------------------------------------------------------------
// One block: histogram -> prefix -> scatter, warp-aggregated atomics.
__global__ void wcss_scatter(const int* __restrict__ y, int N)
{
    __shared__ int cnt[KMAX], off[KMAX];
    const int tid  = threadIdx.x;
    const int lane = tid & 31;

    if (tid < KMAX) { cnt[tid] = 0; g_S2[tid] = 0.0; g_M2[tid] = 0.0; }
    __syncthreads();

    // Histogram: one atomic per (warp, class) per iteration.
    for (int base = 0; base < N; base += blockDim.x) {
        int i = base + tid;
        if (i < N) {
            unsigned act = __activemask();
            int c = y[i] & (KMAX - 1);
            unsigned m = __match_any_sync(act, c);
            if (lane == (__ffs(m) - 1))
                atomicAdd(&cnt[c], __popc(m));
        }
    }
    __syncthreads();

    if (tid == 0) {
        int acc = 0;
        for (int k = 0; k < KMAX; k++) {
            off[k] = acc; g_start[k] = acc; g_cnt[k] = cnt[k];
            acc += cnt[k];
        }
    }
    __syncthreads();

    // Scatter: leader reserves a warp-group range, lanes rank by popc.
    for (int base = 0; base < N; base += blockDim.x) {
        int i = base + tid;
        if (i < N) {
            unsigned act = __activemask();
            int c = y[i] & (KMAX - 1);
            unsigned m = __match_any_sync(act, c);
            int leader = __ffs(m) - 1;
            int rank   = __popc(m & ((1u << lane) - 1u));
            int pos = 0;
            if (lane == leader)
                pos = atomicAdd(&off[c], __popc(m));
            pos = __shfl_sync(m, pos, leader);
            int idx = pos + rank;
            if (idx < NMAX) g_order[idx] = i;
        }
    }
}

// ---------------------------------------------------------------------------
// grid = (colChunks, KMAX). Block (x, c): class c, columns [x*CHUNK, ...),
// loops over ALL rows of class c. Register-complete column sums.
__global__ __launch_bounds__(CHUNK)
void wcss_main(const float* __restrict__ X, int D)
{
    const int c  = blockIdx.y;
    const int cn = g_cnt[c];
    if (cn == 0) return;
    const int st = g_start[c];

    const int tid = threadIdx.x;
    const int d   = blockIdx.x * CHUNK + tid;
    const bool valid = (d < D);

    __shared__ int rows_sh[TILE];

    float s0 = 0.f, s1 = 0.f, s2 = 0.f, s3 = 0.f;
    float q0 = 0.f, q1 = 0.f, q2 = 0.f, q3 = 0.f;

    for (int base = 0; base < cn; base += TILE) {
        const int tl = min(TILE, cn - base);
        __syncthreads();                       // protect rows_sh reuse
        if (tid < tl) rows_sh[tid] = g_order[st + base + tid];
        __syncthreads();

        if (valid) {
            int i = 0;
            for (; i + BATCH <= tl; i += BATCH) {
                float x[BATCH];
                #pragma unroll
                for (int u = 0; u < BATCH; u++)
                    x[u] = __ldg(&X[(size_t)rows_sh[i + u] * D + d]);
                #pragma unroll
                for (int u = 0; u < BATCH; u += 4) {
                    s0 += x[u];     q0 = fmaf(x[u],     x[u],     q0);
                    s1 += x[u + 1]; q1 = fmaf(x[u + 1], x[u + 1], q1);
                    s2 += x[u + 2]; q2 = fmaf(x[u + 2], x[u + 2], q2);
                    s3 += x[u + 3]; q3 = fmaf(x[u + 3], x[u + 3], q3);
                }
            }
            for (; i < tl; i++) {
                float xv = __ldg(&X[(size_t)rows_sh[i] * D + d]);
                s0 += xv; q0 = fmaf(xv, xv, q0);
            }
        }
    }

    // Per-thread: full column sum -> m2 contribution; sumsq q.
    float s  = (s0 + s1) + (s2 + s3);
    float m2 = valid ? s * s : 0.f;
    float q  = (q0 + q1) + (q2 + q3);

    #pragma unroll
    for (int o = 16; o > 0; o >>= 1) {
        m2 += __shfl_down_sync(0xffffffffu, m2, o);
        q  += __shfl_down_sync(0xffffffffu, q,  o);
    }

    __shared__ float ms[CHUNK / 32], qs[CHUNK / 32];
    if ((tid & 31) == 0) { ms[tid >> 5] = m2; qs[tid >> 5] = q; }
    __syncthreads();
    if (tid < 32) {
        float mv = (tid < CHUNK / 32) ? ms[tid] : 0.f;
        float qv = (tid < CHUNK / 32) ? qs[tid] : 0.f;
        #pragma unroll
        for (int o = CHUNK / 64; o > 0; o >>= 1) {
            mv += __shfl_down_sync(0xffffffffu, mv, o);
            qv += __shfl_down_sync(0xffffffffu, qv, o);
        }
        if (tid == 0) {
            atomicAdd(&g_M2[c], (double)mv);
            atomicAdd(&g_S2[c], (double)qv);
        }
    }
}

// ---------------------------------------------------------------------------
__global__ void wcss_final(int D, float* __restrict__ out)
{
    if (threadIdx.x == 0) {
        double total = 0.0;
        int    nc    = 0;
        for (int k = 0; k < KMAX; k++) {
            int c = g_cnt[k];
            if (c == 0) continue;
            double n = (double)c;
            total += (g_S2[k] - g_M2[k] / n) / (n * (double)D);
            nc++;
        }
        out[0] = (float)(total / (double)(nc > 0 ? nc : 1));
    }
}

// ---------------------------------------------------------------------------
extern "C" void kernel_launch(void* const* d_in, const int* in_sizes, int n_in,
                              void* d_out, int out_size)
{
    const float* X   = (const float*)d_in[0];
    const int*   y   = (const int*)d_in[1];   // int32 (JAX x64 disabled)
    float*       out = (float*)d_out;

    const int total = in_sizes[0];          // N * C * T
    const int N     = in_sizes[1];          // 8192
    const int D     = total / N;            // 6144

    wcss_scatter<<<1, 1024>>>(y, N);

    {
        int chunks = (D + CHUNK - 1) / CHUNK;   // 48
        dim3 grid(chunks, KMAX);
        wcss_main<<<grid, CHUNK>>>(X, D);
    }

    wcss_final<<<1, 32>>>(D, out);
}

// round 7
// speedup vs baseline: 1.7528x; 1.7528x over previous
#include <cuda_runtime.h>
#include <cuda_bf16.h>

// WCSS: loss = mean_k [ (S2_k - ||S1_k||^2 / n_k) / (n_k * D) ]
//
// R6 post-mortem: match_any scatter regressed (24us); BATCH=32 overflowed the
// ~248-line L1tex queue. R7: revert to CHUNK=256/BATCH(PF)=16, add explicit
// double-buffer software pipelining (no drain bubble between batches), stage
// the whole class row-list in smem once, and use per-warp private histogram
// rows in scatter (no cross-warp atomic contention).

#define CHUNK 256          // columns per block == threads per block
#define SROWS 4096         // row ids staged per segment (16KB smem)
#define PF    16           // pipelined loads per stage
#define KMAX  16           // max classes (problem uses 10)
#define NMAX  16384        // max N (problem uses 8192)
#define SW    32           // warps in scatter block

__device__ double g_S2[KMAX];     // per-class sum of squares
__device__ double g_M2[KMAX];     // per-class ||S1_k||^2
__device__ int    g_order[NMAX];  // row ids grouped by class
__device__ int    g_cnt[KMAX];
__device__ int    g_start[KMAX];

// ---------------------------------------------------------------------------
// One block (1024 thr = 32 warps): per-warp private histograms -> prefix ->
// scatter through per-warp running offsets. No cross-warp atomic contention.
__global__ void wcss_scatter(const int* __restrict__ y, int N)
{
    __shared__ int wcnt[SW][KMAX];    // per-warp histogram / running offset
    __shared__ int cls_tot[KMAX];
    __shared__ int start_sh[KMAX];

    const int tid  = threadIdx.x;
    const int w    = tid >> 5;
    const int lane = tid & 31;

    if (lane < KMAX) wcnt[w][lane] = 0;
    if (tid < KMAX) { g_S2[tid] = 0.0; g_M2[tid] = 0.0; }
    __syncthreads();

    // Phase 1: per-warp histogram (atomics only within own row).
    for (int i = tid; i < N; i += blockDim.x)
        atomicAdd(&wcnt[w][y[i] & (KMAX - 1)], 1);
    __syncthreads();

    // Phase 2: within-class exclusive prefix over warps (thread k owns class k).
    if (tid < KMAX) {
        int acc = 0;
        for (int w2 = 0; w2 < SW; w2++) {
            int v = wcnt[w2][tid];
            wcnt[w2][tid] = acc;      // exclusive prefix within class
            acc += v;
        }
        cls_tot[tid] = acc;
    }
    __syncthreads();
    if (tid == 0) {
        int acc = 0;
        for (int k = 0; k < KMAX; k++) {
            start_sh[k] = acc; g_start[k] = acc; g_cnt[k] = cls_tot[k];
            acc += cls_tot[k];
        }
    }
    __syncthreads();
    if (lane < KMAX) wcnt[w][lane] += start_sh[lane];  // absolute running offset
    __syncthreads();

    // Phase 3: scatter via per-warp running offsets.
    for (int i = tid; i < N; i += blockDim.x) {
        int c   = y[i] & (KMAX - 1);
        int pos = atomicAdd(&wcnt[w][c], 1);
        if (pos < NMAX) g_order[pos] = i;
    }
}

// ---------------------------------------------------------------------------
// grid = (colChunks, KMAX). Block (x, c): class c, columns [x*CHUNK ...).
// Whole class row-list staged in smem; double-buffered PF-deep load pipeline
// keeps loads continuously in flight (no batch drain bubble).
__global__ __launch_bounds__(CHUNK)
void wcss_main(const float* __restrict__ X, int D)
{
    const int c  = blockIdx.y;
    const int cn = g_cnt[c];
    if (cn == 0) return;
    const int st = g_start[c];

    const int tid = threadIdx.x;
    const int d   = blockIdx.x * CHUNK + tid;
    const bool valid = (d < D);

    __shared__ int rows_sh[SROWS];

    float s0 = 0.f, s1 = 0.f, s2 = 0.f, s3 = 0.f;
    float q0 = 0.f, q1 = 0.f, q2 = 0.f, q3 = 0.f;

    for (int seg = 0; seg < cn; seg += SROWS) {
        const int len = min(SROWS, cn - seg);
        __syncthreads();
        for (int i = tid; i < len; i += CHUNK)
            rows_sh[i] = g_order[st + seg + i];
        __syncthreads();

        if (!valid) continue;
        const float* __restrict__ base = X + d;

        float buf[PF];
        const int np = min(PF, len);
        #pragma unroll
        for (int u = 0; u < PF; u++)
            buf[u] = (u < np) ? __ldg(base + (size_t)rows_sh[u] * D) : 0.f;

        int i = 0;
        for (; i + 2 * PF <= len; i += PF) {
            float nxt[PF];
            #pragma unroll
            for (int u = 0; u < PF; u++)          // issue next batch FIRST
                nxt[u] = __ldg(base + (size_t)rows_sh[i + PF + u] * D);
            #pragma unroll
            for (int u = 0; u < PF; u += 4) {     // consume current batch
                s0 += buf[u];     q0 = fmaf(buf[u],     buf[u],     q0);
                s1 += buf[u + 1]; q1 = fmaf(buf[u + 1], buf[u + 1], q1);
                s2 += buf[u + 2]; q2 = fmaf(buf[u + 2], buf[u + 2], q2);
                s3 += buf[u + 3]; q3 = fmaf(buf[u + 3], buf[u + 3], q3);
            }
            #pragma unroll
            for (int u = 0; u < PF; u++)
                buf[u] = nxt[u];
        }

        // Drain the buffer (valid entries: min(PF, len - i)).
        const int inbuf = min(PF, len - i);
        #pragma unroll
        for (int u = 0; u < PF; u++) {
            if (u < inbuf) {
                s0 += buf[u]; q0 = fmaf(buf[u], buf[u], q0);
            }
        }
        // Leftover rows beyond the buffer.
        for (int j = i + inbuf; j < len; j++) {
            float xv = __ldg(base + (size_t)rows_sh[j] * D);
            s1 += xv; q1 = fmaf(xv, xv, q1);
        }
    }

    // Per-thread: full column sum -> m2 contribution; sumsq q.
    float s  = (s0 + s1) + (s2 + s3);
    float m2 = valid ? s * s : 0.f;
    float q  = (q0 + q1) + (q2 + q3);

    #pragma unroll
    for (int o = 16; o > 0; o >>= 1) {
        m2 += __shfl_down_sync(0xffffffffu, m2, o);
        q  += __shfl_down_sync(0xffffffffu, q,  o);
    }

    __shared__ float ms[CHUNK / 32], qs[CHUNK / 32];
    if ((tid & 31) == 0) { ms[tid >> 5] = m2; qs[tid >> 5] = q; }
    __syncthreads();
    if (tid < 32) {
        float mv = (tid < CHUNK / 32) ? ms[tid] : 0.f;
        float qv = (tid < CHUNK / 32) ? qs[tid] : 0.f;
        #pragma unroll
        for (int o = CHUNK / 64; o > 0; o >>= 1) {
            mv += __shfl_down_sync(0xffffffffu, mv, o);
            qv += __shfl_down_sync(0xffffffffu, qv, o);
        }
        if (tid == 0) {
            atomicAdd(&g_M2[c], (double)mv);
            atomicAdd(&g_S2[c], (double)qv);
        }
    }
}

// ---------------------------------------------------------------------------
__global__ void wcss_final(int D, float* __restrict__ out)
{
    if (threadIdx.x == 0) {
        double total = 0.0;
        int    nc    = 0;
        for (int k = 0; k < KMAX; k++) {
            int c = g_cnt[k];
            if (c == 0) continue;
            double n = (double)c;
            total += (g_S2[k] - g_M2[k] / n) / (n * (double)D);
            nc++;
        }
        out[0] = (float)(total / (double)(nc > 0 ? nc : 1));
    }
}

// ---------------------------------------------------------------------------
extern "C" void kernel_launch(void* const* d_in, const int* in_sizes, int n_in,
                              void* d_out, int out_size)
{
    const float* X   = (const float*)d_in[0];
    const int*   y   = (const int*)d_in[1];   // int32 (JAX x64 disabled)
    float*       out = (float*)d_out;

    const int total = in_sizes[0];          // N * C * T
    const int N     = in_sizes[1];          // 8192
    const int D     = total / N;            // 6144

    wcss_scatter<<<1, 1024>>>(y, N);

    {
        int chunks = (D + CHUNK - 1) / CHUNK;   // 24
        dim3 grid(chunks, KMAX);
        wcss_main<<<grid, CHUNK>>>(X, D);
    }

    wcss_final<<<1, 32>>>(D, out);
}